// round 12
// baseline (speedup 1.0000x reference)
#include <cuda_runtime.h>
#include <cuda_fp16.h>
#include <cstdint>
#include <cstddef>

// ---------------- problem constants ----------------
#define NN     16384
#define DIN    1024
#define HH     4
#define CC     128
#define HC     512
#define EE     262144
#define ETOT   (EE + NN)
#define BB     16
#define NODES  1024
#define NBLK   64

// ---------------- device scratch ----------------
__device__ __half g_Hh[(size_t)NN * HC];     // GEMM output, fp16
__device__ __half g_Af[(size_t)NN * DIN];    // A operand (x, then h1)
__device__ __half g_Bf[DIN * HC];            // W operand
__device__ float  g_as[NN * HH];
__device__ float  g_ad[NN * HH];
__device__ int    g_src[ETOT];
__device__ int    g_dst[ETOT];
__device__ int    g_csrc[ETOT];
__device__ int    g_deg[NN];
__device__ int    g_cur[NN];
__device__ int    g_off[NN + 1];
__device__ int    g_bsum[NBLK];
__device__ int    g_is64;
__device__ float  g_x2[BB * NODES];
__device__ float  g_e1[BB * 512];
__device__ float  g_e2[BB * 256];
__device__ float  g_e3[BB * 128];
__device__ float  g_e4[BB * 64];

// ---------------- helpers ----------------
__device__ __forceinline__ float wsum(float v) {
#pragma unroll
    for (int o = 16; o > 0; o >>= 1) v += __shfl_xor_sync(0xffffffffu, v, o);
    return v;
}
__device__ __forceinline__ float wmax(float v) {
#pragma unroll
    for (int o = 16; o > 0; o >>= 1) v = fmaxf(v, __shfl_xor_sync(0xffffffffu, v, o));
    return v;
}
__device__ __forceinline__ float lrelu(float x) { return (x > 0.f) ? x : 0.2f * x; }
__device__ __forceinline__ void cp16(unsigned s, const void* g) {
    asm volatile("cp.async.cg.shared.global [%0], [%1], 16;" :: "r"(s), "l"(g));
}
__device__ __forceinline__ void ldsm4(unsigned* r, unsigned a) {
    asm volatile("ldmatrix.sync.aligned.m8n8.x4.shared.b16 {%0,%1,%2,%3}, [%4];"
                 : "=r"(r[0]), "=r"(r[1]), "=r"(r[2]), "=r"(r[3]) : "r"(a));
}
__device__ __forceinline__ void ldsm4t(unsigned* r, unsigned a) {
    asm volatile("ldmatrix.sync.aligned.m8n8.x4.trans.shared.b16 {%0,%1,%2,%3}, [%4];"
                 : "=r"(r[0]), "=r"(r[1]), "=r"(r[2]), "=r"(r[3]) : "r"(a));
}
__device__ __forceinline__ void mma16816(float* c, const unsigned* a, const unsigned* b) {
    asm volatile("mma.sync.aligned.m16n8k16.row.col.f32.f16.f16.f32 "
                 "{%0,%1,%2,%3}, {%4,%5,%6,%7}, {%8,%9}, {%0,%1,%2,%3};"
                 : "+f"(c[0]), "+f"(c[1]), "+f"(c[2]), "+f"(c[3])
                 : "r"(a[0]), "r"(a[1]), "r"(a[2]), "r"(a[3]), "r"(b[0]), "r"(b[1]));
}
__device__ __forceinline__ unsigned pack_h2(float a, float b) {
    __half2 t = __floats2half2_rn(a, b);
    return *(unsigned*)&t;
}

// ---------------- fp32 -> fp16 convert ----------------
__global__ void cvt_kernel(const float* __restrict__ x, __half* __restrict__ o) {
    const size_t i = (size_t)blockIdx.x * blockDim.x + threadIdx.x;
    const float4 v = ((const float4*)x)[i];
    ((uint2*)o)[i] = make_uint2(pack_h2(v.x, v.y), pack_h2(v.z, v.w));
}

// ---------------- fp16 tensor GEMM + fused alpha dots; fp16 C store ----------------
__global__ __launch_bounds__(256)
void gemm_fp16(const __half* __restrict__ A, const __half* __restrict__ B,
               __half* __restrict__ C, int M, int N, int K,
               const float* __restrict__ attS, const float* __restrict__ attD) {
    extern __shared__ __half sm[];
    __shared__ float s_att[2][128];
    __shared__ float sredS[2][128], sredD[2][128];
    const int tid   = threadIdx.x;
    const int mBase = blockIdx.y * 128;
    const int nBase = blockIdx.x * 128;
    const unsigned sbase = (unsigned)__cvta_generic_to_shared(sm);

    if (tid < 128) {
        s_att[0][tid] = attS[nBase + tid];
        s_att[1][tid] = attD[nBase + tid];
    }

    const int wid = tid >> 5, lane = tid & 31;
    const int wm = wid & 3;
    const int wn = wid >> 2;

    float acc[2][8][4];
#pragma unroll
    for (int i = 0; i < 2; i++)
#pragma unroll
        for (int j = 0; j < 8; j++)
#pragma unroll
            for (int k = 0; k < 4; k++) acc[i][j][k] = 0.f;

    auto load_stage = [&](int stage, int kt) {
        const int kb = kt * 32;
        const unsigned aBase = sbase + stage * 8192;
        const unsigned bBase = sbase + 32768 + stage * 8192;
#pragma unroll
        for (int i = 0; i < 2; i++) {
            const int chunk = tid + (i << 8);
            const int row = chunk >> 2, u = chunk & 3;
            const int su = u ^ ((row >> 1) & 3);
            cp16(aBase + row * 64 + su * 16, A + (size_t)(mBase + row) * K + kb + u * 8);
        }
#pragma unroll
        for (int i = 0; i < 2; i++) {
            const int chunk = tid + (i << 8);
            const int row = chunk >> 4, u = chunk & 15;
            const int su = u ^ (row & 7);
            cp16(bBase + row * 256 + su * 16, B + (size_t)(kb + row) * N + nBase + u * 8);
        }
    };

    const int nk = K >> 5;
    load_stage(0, 0);
    asm volatile("cp.async.commit_group;");
    load_stage(1, 1);
    asm volatile("cp.async.commit_group;");
    load_stage(2, 2);
    asm volatile("cp.async.commit_group;");

    for (int kt = 0; kt < nk; kt++) {
        if (kt + 3 < nk) load_stage((kt + 3) & 3, kt + 3);
        asm volatile("cp.async.commit_group;");
        asm volatile("cp.async.wait_group 3;");
        __syncthreads();

        const int stage = kt & 3;
        const unsigned aStage = sbase + stage * 8192;
        const unsigned bStage = sbase + 32768 + stage * 8192;
#pragma unroll
        for (int kk = 0; kk < 2; kk++) {
            unsigned ah[2][4], bh[4][4];
#pragma unroll
            for (int mt = 0; mt < 2; mt++) {
                const int row = wm * 32 + mt * 16 + (lane & 15);
                const int u = (kk * 2 + (lane >> 4)) ^ ((row >> 1) & 3);
                ldsm4(ah[mt], aStage + row * 64 + u * 16);
            }
#pragma unroll
            for (int nt = 0; nt < 4; nt++) {
                const int row = kk * 16 + (lane & 15);
                const int u = (wn * 8 + nt * 2 + (lane >> 4)) ^ (row & 7);
                ldsm4t(bh[nt], bStage + row * 256 + u * 16);
            }
#pragma unroll
            for (int mt = 0; mt < 2; mt++)
#pragma unroll
                for (int n8 = 0; n8 < 8; n8++)
                    mma16816(acc[mt][n8], ah[mt], &bh[n8 >> 1][(n8 & 1) * 2]);
        }
        __syncthreads();
    }

    // fp16 C store + fused alpha partials (alphas from fp32 accumulators)
    float psS[4] = {0.f, 0.f, 0.f, 0.f};
    float psD[4] = {0.f, 0.f, 0.f, 0.f};
#pragma unroll
    for (int mt = 0; mt < 2; mt++) {
#pragma unroll
        for (int n8 = 0; n8 < 8; n8++) {
            const int row0 = mBase + wm * 32 + mt * 16 + (lane >> 2);
            const int colL = wn * 64 + n8 * 8 + (lane & 3) * 2;
            *(unsigned*)&C[(size_t)row0 * N + nBase + colL]       = pack_h2(acc[mt][n8][0], acc[mt][n8][1]);
            *(unsigned*)&C[(size_t)(row0 + 8) * N + nBase + colL] = pack_h2(acc[mt][n8][2], acc[mt][n8][3]);
            const float aS0 = s_att[0][colL], aS1 = s_att[0][colL + 1];
            const float aD0 = s_att[1][colL], aD1 = s_att[1][colL + 1];
            psS[mt * 2 + 0] += acc[mt][n8][0] * aS0 + acc[mt][n8][1] * aS1;
            psS[mt * 2 + 1] += acc[mt][n8][2] * aS0 + acc[mt][n8][3] * aS1;
            psD[mt * 2 + 0] += acc[mt][n8][0] * aD0 + acc[mt][n8][1] * aD1;
            psD[mt * 2 + 1] += acc[mt][n8][2] * aD0 + acc[mt][n8][3] * aD1;
        }
    }
#pragma unroll
    for (int o = 1; o <= 2; o <<= 1) {
#pragma unroll
        for (int k = 0; k < 4; k++) {
            psS[k] += __shfl_xor_sync(0xffffffffu, psS[k], o);
            psD[k] += __shfl_xor_sync(0xffffffffu, psD[k], o);
        }
    }
    if ((lane & 3) == 0) {
        const int q = lane >> 2;
#pragma unroll
        for (int mt = 0; mt < 2; mt++) {
            sredS[wn][wm * 32 + mt * 16 + q]     = psS[mt * 2 + 0];
            sredS[wn][wm * 32 + mt * 16 + q + 8] = psS[mt * 2 + 1];
            sredD[wn][wm * 32 + mt * 16 + q]     = psD[mt * 2 + 0];
            sredD[wn][wm * 32 + mt * 16 + q + 8] = psD[mt * 2 + 1];
        }
    }
    __syncthreads();
    if (tid < 128) {
        const int row = mBase + tid;
        g_as[row * HH + blockIdx.x] = sredS[0][tid] + sredS[1][tid];
        g_ad[row * HH + blockIdx.x] = sredD[0][tid] + sredD[1][tid];
    }
}

// ---------------- CSR build ----------------
__global__ void detect_zero(const int* __restrict__ buf) {
    const int i = blockIdx.x * 256 + threadIdx.x;
    if (i < NN) { g_deg[i] = 0; g_cur[i] = 0; }
    if (blockIdx.x == 0) {
        __shared__ int sh[256];
        int v = 0;
        for (int k = threadIdx.x; k < 8192; k += 256) v |= buf[2 * k + 1];
        sh[threadIdx.x] = v;
        __syncthreads();
        for (int s = 128; s > 0; s >>= 1) {
            if (threadIdx.x < s) sh[threadIdx.x] |= sh[threadIdx.x + s];
            __syncthreads();
        }
        if (threadIdx.x == 0) g_is64 = (sh[0] == 0) ? 1 : 0;
    }
}

__global__ void convert_kernel(const int* __restrict__ buf) {
    const int e = blockIdx.x * blockDim.x + threadIdx.x;
    if (e >= ETOT) return;
    int s, d;
    if (e >= EE) { s = d = e - EE; }
    else if (g_is64) { s = buf[2 * e]; d = buf[2 * (EE + e)]; }
    else             { s = buf[e];     d = buf[EE + e]; }
    g_src[e] = s; g_dst[e] = d;
    atomicAdd(&g_deg[d], 1);
}

__global__ void scan_blocks() {
    const int tid = threadIdx.x, lane = tid & 31, wid = tid >> 5;
    const int i = blockIdx.x * 256 + tid;
    const int v = g_deg[i];
    int x = v;
#pragma unroll
    for (int o = 1; o < 32; o <<= 1) {
        const int y = __shfl_up_sync(0xffffffffu, x, o);
        if (lane >= o) x += y;
    }
    __shared__ int ws[8], wsx[8];
    if (lane == 31) ws[wid] = x;
    __syncthreads();
    if (tid < 8) {
        int ex = 0;
        for (int k = 0; k < tid; k++) ex += ws[k];
        wsx[tid] = ex;
        if (tid == 7) g_bsum[blockIdx.x] = ex + ws[7];
    }
    __syncthreads();
    g_off[i] = wsx[wid] + (x - v);
}

__global__ void scan_bsum() {
    const int tid = threadIdx.x;
    const int v = g_bsum[tid];
    int x = v;
#pragma unroll
    for (int o = 1; o < 32; o <<= 1) {
        const int y = __shfl_up_sync(0xffffffffu, x, o);
        if ((tid & 31) >= o) x += y;
    }
    __shared__ int w0;
    if (tid == 31) w0 = x;
    __syncthreads();
    if (tid >= 32) x += w0;
    g_bsum[tid] = x - v;
    if (tid == 0) g_off[NN] = ETOT;
}

__global__ void scan_add() {
    const int i = blockIdx.x * 256 + threadIdx.x;
    g_off[i] += g_bsum[blockIdx.x];
}

__global__ void scatter_kernel() {
    const int e = blockIdx.x * blockDim.x + threadIdx.x;
    if (e >= ETOT) return;
    const int d = g_dst[e];
    const int pos = atomicAdd(&g_cur[d], 1);
    g_csrc[g_off[d] + pos] = g_src[e];
}

// ---------------- fused softmax + aggregate: WARP PER NODE (all 4 heads) ----------------
// lane owns 16 contiguous channels; head of lane = lane>>3.
// pass 1: online softmax stats for all 4 heads (one float4 g_as load per edge)
// pass 2: per edge 2x uint4 fp16 loads per lane, weight via 4 shfls + select
// mode 0: elu(acc+bias) -> fp16 g_Af ; mode 1: full-row dot with p2w -> g_x2[n]
__global__ __launch_bounds__(256)
void csr_aggregate(const float* __restrict__ bias, const float* __restrict__ pw,
                   const float* __restrict__ pb, int mode) {
    const int n = blockIdx.x * 8 + (threadIdx.x >> 5);
    const int lane = threadIdx.x & 31;
    const int h = lane >> 3;
    const int off0 = g_off[n];
    const int deg  = g_off[n + 1] - off0;
    const float4 adp = *(const float4*)&g_ad[n * HH];

    // pass 1: online stats for 4 heads
    float m0 = -1e30f, m1 = -1e30f, m2 = -1e30f, m3 = -1e30f;
    float s0 = 0.f, s1 = 0.f, s2 = 0.f, s3 = 0.f;
    for (int j = lane; j < deg; j += 32) {
        const int src = g_csrc[off0 + j];
        const float4 a = *(const float4*)&g_as[src * HH];
        const float x0 = lrelu(a.x + adp.x), x1 = lrelu(a.y + adp.y);
        const float x2 = lrelu(a.z + adp.z), x3 = lrelu(a.w + adp.w);
        if (x0 > m0) { s0 = s0 * __expf(m0 - x0) + 1.f; m0 = x0; } else s0 += __expf(x0 - m0);
        if (x1 > m1) { s1 = s1 * __expf(m1 - x1) + 1.f; m1 = x1; } else s1 += __expf(x1 - m1);
        if (x2 > m2) { s2 = s2 * __expf(m2 - x2) + 1.f; m2 = x2; } else s2 += __expf(x2 - m2);
        if (x3 > m3) { s3 = s3 * __expf(m3 - x3) + 1.f; m3 = x3; } else s3 += __expf(x3 - m3);
    }
    const float M0 = wmax(m0), M1 = wmax(m1), M2 = wmax(m2), M3 = wmax(m3);
    s0 *= __expf(m0 - M0); s1 *= __expf(m1 - M1);
    s2 *= __expf(m2 - M2); s3 *= __expf(m3 - M3);
    const float i0 = 1.f / (wsum(s0) + 1e-16f);
    const float i1 = 1.f / (wsum(s1) + 1e-16f);
    const float i2 = 1.f / (wsum(s2) + 1e-16f);
    const float i3 = 1.f / (wsum(s3) + 1e-16f);

    // pass 2: gather
    float acc[16];
#pragma unroll
    for (int t = 0; t < 16; t++) acc[t] = 0.f;
    const __half* hbase = g_Hh + lane * 16;

    for (int base = 0; base < deg; base += 32) {
        const int cnt = min(32, deg - base);
        int src = 0;
        float4 w4 = make_float4(0.f, 0.f, 0.f, 0.f);
        if (lane < cnt) {
            src = g_csrc[off0 + base + lane];
            const float4 a = *(const float4*)&g_as[src * HH];
            w4.x = __expf(lrelu(a.x + adp.x) - M0) * i0;
            w4.y = __expf(lrelu(a.y + adp.y) - M1) * i1;
            w4.z = __expf(lrelu(a.z + adp.z) - M2) * i2;
            w4.w = __expf(lrelu(a.w + adp.w) - M3) * i3;
        }
        for (int j = 0; j < cnt; j++) {
            const int   ss = __shfl_sync(0xffffffffu, src, j);
            const float wx = __shfl_sync(0xffffffffu, w4.x, j);
            const float wy = __shfl_sync(0xffffffffu, w4.y, j);
            const float wz = __shfl_sync(0xffffffffu, w4.z, j);
            const float ww = __shfl_sync(0xffffffffu, w4.w, j);
            const float wsel = (h == 0) ? wx : (h == 1) ? wy : (h == 2) ? wz : ww;
            const __half* hp = hbase + (size_t)ss * HC;
            const uint4 p0 = *(const uint4*)hp;
            const uint4 p1 = *(const uint4*)(hp + 8);
            const __half2* q0 = (const __half2*)&p0;
            const __half2* q1 = (const __half2*)&p1;
#pragma unroll
            for (int t = 0; t < 4; t++) {
                const float2 f0 = __half22float2(q0[t]);
                const float2 f1 = __half22float2(q1[t]);
                acc[2 * t]     += f0.x * wsel;
                acc[2 * t + 1] += f0.y * wsel;
                acc[8 + 2 * t] += f1.x * wsel;
                acc[9 + 2 * t] += f1.y * wsel;
            }
        }
    }

    // epilogue: bias + ELU on lane's 16 channels
    float v[16];
    const float4* bq = (const float4*)(bias + lane * 16);
#pragma unroll
    for (int q = 0; q < 4; q++) {
        const float4 b4 = bq[q];
        v[4 * q + 0] = acc[4 * q + 0] + b4.x;
        v[4 * q + 1] = acc[4 * q + 1] + b4.y;
        v[4 * q + 2] = acc[4 * q + 2] + b4.z;
        v[4 * q + 3] = acc[4 * q + 3] + b4.w;
    }
#pragma unroll
    for (int t = 0; t < 16; t++) v[t] = (v[t] > 0.f) ? v[t] : expm1f(v[t]);

    if (mode == 0) {
        unsigned o[8];
#pragma unroll
        for (int t = 0; t < 8; t++) o[t] = pack_h2(v[2 * t], v[2 * t + 1]);
        __half* dst = g_Af + (size_t)n * HC + lane * 16;
        *(uint4*)dst       = make_uint4(o[0], o[1], o[2], o[3]);
        *(uint4*)(dst + 8) = make_uint4(o[4], o[5], o[6], o[7]);
    } else {
        const float4* pq = (const float4*)(pw + lane * 16);
        float dot = 0.f;
#pragma unroll
        for (int q = 0; q < 4; q++) {
            const float4 p4 = pq[q];
            dot += v[4 * q + 0] * p4.x + v[4 * q + 1] * p4.y
                 + v[4 * q + 2] * p4.z + v[4 * q + 3] * p4.w;
        }
        dot = wsum(dot);
        if (lane == 0) g_x2[n] = dot + pb[0];
    }
}

// ---------------- layer norm ----------------
__global__ void ln_kernel(const float* __restrict__ g, const float* __restrict__ be,
                          float* __restrict__ out) {
    const int bb = blockIdx.x, tid = threadIdx.x;
    const int lane = tid & 31, wid = tid >> 5;
    float s = 0.f, s2 = 0.f;
    for (int i = tid; i < NODES; i += 256) {
        const float v = g_x2[bb * NODES + i];
        s += v; s2 += v * v;
    }
    s = wsum(s); s2 = wsum(s2);
    __shared__ float shs[8], shs2[8];
    if (lane == 0) { shs[wid] = s; shs2[wid] = s2; }
    __syncthreads();
    __shared__ float smu, srv;
    if (tid == 0) {
        float S = 0.f, S2 = 0.f;
        for (int w = 0; w < 8; w++) { S += shs[w]; S2 += shs2[w]; }
        const float mu = S / NODES;
        smu = mu;
        srv = rsqrtf(S2 / NODES - mu * mu + 1e-5f);
    }
    __syncthreads();
    const float mu = smu, rv = srv;
    for (int i = tid; i < NODES; i += 256) {
        const float v = (g_x2[bb * NODES + i] - mu) * rv * g[i] + be[i];
        out[bb * NODES + i] = v;
        g_x2[bb * NODES + i] = v;
    }
}

// ---------------- small FC ----------------
__global__ void fc_kernel(const float* __restrict__ in, const float* __restrict__ W,
                          const float* __restrict__ bias, float* __restrict__ out,
                          int Din, int Dout, int act) {
    const int j = blockIdx.x * blockDim.x + threadIdx.x;
    const int b = blockIdx.y;
    if (j >= Dout) return;
    const float* ir = in + (size_t)b * Din;
    float s = bias[j];
    for (int k = 0; k < Din; k++) s += ir[k] * W[(size_t)k * Dout + j];
    if (act) s = (s > 0.f) ? s : expm1f(s);
    out[b * Dout + j] = s;
}

// ---------------- final ----------------
__global__ void final_kernel(const float* __restrict__ lw, const float* __restrict__ lb,
                             float* __restrict__ out) {
    const int b = blockIdx.x, tid = threadIdx.x;
    const float v = g_e4[b * 64 + tid];
    out[BB * NODES + b * 64 + tid] = v;
    float p = v * lw[tid];
#pragma unroll
    for (int o = 16; o > 0; o >>= 1) p += __shfl_xor_sync(0xffffffffu, p, o);
    __shared__ float sh[2];
    if ((tid & 31) == 0) sh[tid >> 5] = p;
    __syncthreads();
    if (tid == 0) out[BB * NODES + BB * 64 + b] = sh[0] + sh[1] + lb[0];
}

// ---------------- launch ----------------
extern "C" void kernel_launch(void* const* d_in, const int* in_sizes, int n_in,
                              void* d_out, int out_size) {
    const float* x     = (const float*)d_in[0];
    const int*   eibuf = (const int*)d_in[1];
    const float* W1   = (const float*)d_in[3];
    const float* as1  = (const float*)d_in[4];
    const float* ad1  = (const float*)d_in[5];
    const float* b1   = (const float*)d_in[6];
    const float* W2   = (const float*)d_in[7];
    const float* as2  = (const float*)d_in[8];
    const float* ad2  = (const float*)d_in[9];
    const float* b2   = (const float*)d_in[10];
    const float* p2w  = (const float*)d_in[13];
    const float* p2b  = (const float*)d_in[14];
    const float* ln_g = (const float*)d_in[15];
    const float* ln_b = (const float*)d_in[16];
    const float* fw1  = (const float*)d_in[17];
    const float* fb1  = (const float*)d_in[18];
    const float* fw2  = (const float*)d_in[19];
    const float* fb2  = (const float*)d_in[20];
    const float* fw3  = (const float*)d_in[21];
    const float* fb3  = (const float*)d_in[22];
    const float* fw4  = (const float*)d_in[23];
    const float* fb4  = (const float*)d_in[24];
    const float* lw   = (const float*)d_in[25];
    const float* lb   = (const float*)d_in[26];
    float* out = (float*)d_out;

    float *px2, *pe1, *pe2, *pe3, *pe4;
    __half *pHh, *pAf, *pBf;
    cudaGetSymbolAddress((void**)&pHh, g_Hh);
    cudaGetSymbolAddress((void**)&pAf, g_Af);
    cudaGetSymbolAddress((void**)&pBf, g_Bf);
    cudaGetSymbolAddress((void**)&px2, g_x2);
    cudaGetSymbolAddress((void**)&pe1, g_e1);
    cudaGetSymbolAddress((void**)&pe2, g_e2);
    cudaGetSymbolAddress((void**)&pe3, g_e3);
    cudaGetSymbolAddress((void**)&pe4, g_e4);

    cudaFuncSetAttribute(gemm_fp16, cudaFuncAttributeMaxDynamicSharedMemorySize, 65536);

    const int eblocks = (ETOT + 255) / 256;
    const dim3 gemm_grid(HC / 128, NN / 128);

    // launch order: gemm_fp16 (layer 1) is launch index 5 for ncu -s 5
    cvt_kernel<<<(NN * DIN / 4) / 256, 256>>>(x, pAf);                          // 0
    cvt_kernel<<<(DIN * HC / 4) / 256, 256>>>(W1, pBf);                         // 1
    detect_zero<<<NBLK, 256>>>(eibuf);                                          // 2
    convert_kernel<<<eblocks, 256>>>(eibuf);                                    // 3
    scan_blocks<<<NBLK, 256>>>();                                               // 4
    gemm_fp16<<<gemm_grid, 256, 65536>>>(pAf, pBf, pHh, NN, HC, DIN, as1, ad1); // 5
    scan_bsum<<<1, 64>>>();
    scan_add<<<NBLK, 256>>>();
    scatter_kernel<<<eblocks, 256>>>();
    csr_aggregate<<<NN / 8, 256>>>(b1, nullptr, nullptr, 0);   // fused softmax+gather -> fp16 h1

    // ===== GAT layer 2 =====
    cvt_kernel<<<(HC * HC / 4) / 256, 256>>>(W2, pBf);
    gemm_fp16<<<gemm_grid, 256, 65536>>>(pAf, pBf, pHh, NN, HC, HC, as2, ad2);
    csr_aggregate<<<NN / 8, 256>>>(b2, p2w, p2b, 1);           // fused pool -> g_x2

    // ===== layer norm -> d_out[0:16384) =====
    ln_kernel<<<BB, 256>>>(ln_g, ln_b, out);

    // ===== encoder MLP =====
    fc_kernel<<<dim3(4, BB), 128>>>(px2, fw1, fb1, pe1, 1024, 512, 1);
    fc_kernel<<<dim3(2, BB), 128>>>(pe1, fw2, fb2, pe2, 512, 256, 1);
    fc_kernel<<<dim3(1, BB), 128>>>(pe2, fw3, fb3, pe3, 256, 128, 1);
    fc_kernel<<<dim3(1, BB), 128>>>(pe3, fw4, fb4, pe4, 128, 64, 1);
    final_kernel<<<BB, 64>>>(lw, lb, out);
}

// round 15
// speedup vs baseline: 1.0091x; 1.0091x over previous
#include <cuda_runtime.h>
#include <cuda_fp16.h>
#include <cstdint>
#include <cstddef>

// ---------------- problem constants ----------------
#define NN     16384
#define DIN    1024
#define HH     4
#define CC     128
#define HC     512
#define EE     262144
#define ETOT   (EE + NN)
#define BB     16
#define NODES  1024
#define NBLK   64

// ---------------- device scratch ----------------
__device__ __half g_Hh[(size_t)NN * HC];     // GEMM output, fp16
__device__ __half g_Af[(size_t)NN * DIN];    // A operand (x, then h1)
__device__ __half g_Bf[DIN * HC];            // W operand
__device__ float  g_as[NN * HH];
__device__ float  g_ad[NN * HH];
__device__ int    g_src[ETOT];
__device__ int    g_dst[ETOT];
__device__ int    g_csrc[ETOT];
__device__ int    g_deg[NN];
__device__ int    g_cur[NN];
__device__ int    g_off[NN + 1];
__device__ int    g_bsum[NBLK];
__device__ int    g_is64;
__device__ float  g_x2[BB * NODES];
__device__ float  g_e1[BB * 512];
__device__ float  g_e2[BB * 256];
__device__ float  g_e3[BB * 128];
__device__ float  g_e4[BB * 64];

// ---------------- helpers ----------------
__device__ __forceinline__ float wsum(float v) {
#pragma unroll
    for (int o = 16; o > 0; o >>= 1) v += __shfl_xor_sync(0xffffffffu, v, o);
    return v;
}
__device__ __forceinline__ float wmax(float v) {
#pragma unroll
    for (int o = 16; o > 0; o >>= 1) v = fmaxf(v, __shfl_xor_sync(0xffffffffu, v, o));
    return v;
}
__device__ __forceinline__ float lrelu(float x) { return (x > 0.f) ? x : 0.2f * x; }
__device__ __forceinline__ void cp16(unsigned s, const void* g) {
    asm volatile("cp.async.cg.shared.global [%0], [%1], 16;" :: "r"(s), "l"(g));
}
__device__ __forceinline__ void ldsm4(unsigned* r, unsigned a) {
    asm volatile("ldmatrix.sync.aligned.m8n8.x4.shared.b16 {%0,%1,%2,%3}, [%4];"
                 : "=r"(r[0]), "=r"(r[1]), "=r"(r[2]), "=r"(r[3]) : "r"(a));
}
__device__ __forceinline__ void ldsm4t(unsigned* r, unsigned a) {
    asm volatile("ldmatrix.sync.aligned.m8n8.x4.trans.shared.b16 {%0,%1,%2,%3}, [%4];"
                 : "=r"(r[0]), "=r"(r[1]), "=r"(r[2]), "=r"(r[3]) : "r"(a));
}
__device__ __forceinline__ void mma16816(float* c, const unsigned* a, const unsigned* b) {
    asm volatile("mma.sync.aligned.m16n8k16.row.col.f32.f16.f16.f32 "
                 "{%0,%1,%2,%3}, {%4,%5,%6,%7}, {%8,%9}, {%0,%1,%2,%3};"
                 : "+f"(c[0]), "+f"(c[1]), "+f"(c[2]), "+f"(c[3])
                 : "r"(a[0]), "r"(a[1]), "r"(a[2]), "r"(a[3]), "r"(b[0]), "r"(b[1]));
}
__device__ __forceinline__ unsigned pack_h2(float a, float b) {
    __half2 t = __floats2half2_rn(a, b);
    return *(unsigned*)&t;
}

// ---------------- fp32 -> fp16 convert ----------------
__global__ void cvt_kernel(const float* __restrict__ x, __half* __restrict__ o) {
    const size_t i = (size_t)blockIdx.x * blockDim.x + threadIdx.x;
    const float4 v = ((const float4*)x)[i];
    ((uint2*)o)[i] = make_uint2(pack_h2(v.x, v.y), pack_h2(v.z, v.w));
}

// ---------------- fp16 tensor GEMM + fused alpha dots; fp16 C store ----------------
__global__ __launch_bounds__(256)
void gemm_fp16(const __half* __restrict__ A, const __half* __restrict__ B,
               __half* __restrict__ C, int M, int N, int K,
               const float* __restrict__ attS, const float* __restrict__ attD) {
    extern __shared__ __half sm[];
    __shared__ float s_att[2][128];
    __shared__ float sredS[2][128], sredD[2][128];
    const int tid   = threadIdx.x;
    const int mBase = blockIdx.y * 128;
    const int nBase = blockIdx.x * 128;
    const unsigned sbase = (unsigned)__cvta_generic_to_shared(sm);

    if (tid < 128) {
        s_att[0][tid] = attS[nBase + tid];
        s_att[1][tid] = attD[nBase + tid];
    }

    const int wid = tid >> 5, lane = tid & 31;
    const int wm = wid & 3;
    const int wn = wid >> 2;

    float acc[2][8][4];
#pragma unroll
    for (int i = 0; i < 2; i++)
#pragma unroll
        for (int j = 0; j < 8; j++)
#pragma unroll
            for (int k = 0; k < 4; k++) acc[i][j][k] = 0.f;

    auto load_stage = [&](int stage, int kt) {
        const int kb = kt * 32;
        const unsigned aBase = sbase + stage * 8192;
        const unsigned bBase = sbase + 32768 + stage * 8192;
#pragma unroll
        for (int i = 0; i < 2; i++) {
            const int chunk = tid + (i << 8);
            const int row = chunk >> 2, u = chunk & 3;
            const int su = u ^ ((row >> 1) & 3);
            cp16(aBase + row * 64 + su * 16, A + (size_t)(mBase + row) * K + kb + u * 8);
        }
#pragma unroll
        for (int i = 0; i < 2; i++) {
            const int chunk = tid + (i << 8);
            const int row = chunk >> 4, u = chunk & 15;
            const int su = u ^ (row & 7);
            cp16(bBase + row * 256 + su * 16, B + (size_t)(kb + row) * N + nBase + u * 8);
        }
    };

    const int nk = K >> 5;
    load_stage(0, 0);
    asm volatile("cp.async.commit_group;");
    load_stage(1, 1);
    asm volatile("cp.async.commit_group;");
    load_stage(2, 2);
    asm volatile("cp.async.commit_group;");

    for (int kt = 0; kt < nk; kt++) {
        if (kt + 3 < nk) load_stage((kt + 3) & 3, kt + 3);
        asm volatile("cp.async.commit_group;");
        asm volatile("cp.async.wait_group 3;");
        __syncthreads();

        const int stage = kt & 3;
        const unsigned aStage = sbase + stage * 8192;
        const unsigned bStage = sbase + 32768 + stage * 8192;
#pragma unroll
        for (int kk = 0; kk < 2; kk++) {
            unsigned ah[2][4], bh[4][4];
#pragma unroll
            for (int mt = 0; mt < 2; mt++) {
                const int row = wm * 32 + mt * 16 + (lane & 15);
                const int u = (kk * 2 + (lane >> 4)) ^ ((row >> 1) & 3);
                ldsm4(ah[mt], aStage + row * 64 + u * 16);
            }
#pragma unroll
            for (int nt = 0; nt < 4; nt++) {
                const int row = kk * 16 + (lane & 15);
                const int u = (wn * 8 + nt * 2 + (lane >> 4)) ^ (row & 7);
                ldsm4t(bh[nt], bStage + row * 256 + u * 16);
            }
#pragma unroll
            for (int mt = 0; mt < 2; mt++)
#pragma unroll
                for (int n8 = 0; n8 < 8; n8++)
                    mma16816(acc[mt][n8], ah[mt], &bh[n8 >> 1][(n8 & 1) * 2]);
        }
        __syncthreads();
    }

    // fp16 C store + fused alpha partials (alphas from fp32 accumulators)
    float psS[4] = {0.f, 0.f, 0.f, 0.f};
    float psD[4] = {0.f, 0.f, 0.f, 0.f};
#pragma unroll
    for (int mt = 0; mt < 2; mt++) {
#pragma unroll
        for (int n8 = 0; n8 < 8; n8++) {
            const int row0 = mBase + wm * 32 + mt * 16 + (lane >> 2);
            const int colL = wn * 64 + n8 * 8 + (lane & 3) * 2;
            *(unsigned*)&C[(size_t)row0 * N + nBase + colL]       = pack_h2(acc[mt][n8][0], acc[mt][n8][1]);
            *(unsigned*)&C[(size_t)(row0 + 8) * N + nBase + colL] = pack_h2(acc[mt][n8][2], acc[mt][n8][3]);
            const float aS0 = s_att[0][colL], aS1 = s_att[0][colL + 1];
            const float aD0 = s_att[1][colL], aD1 = s_att[1][colL + 1];
            psS[mt * 2 + 0] += acc[mt][n8][0] * aS0 + acc[mt][n8][1] * aS1;
            psS[mt * 2 + 1] += acc[mt][n8][2] * aS0 + acc[mt][n8][3] * aS1;
            psD[mt * 2 + 0] += acc[mt][n8][0] * aD0 + acc[mt][n8][1] * aD1;
            psD[mt * 2 + 1] += acc[mt][n8][2] * aD0 + acc[mt][n8][3] * aD1;
        }
    }
#pragma unroll
    for (int o = 1; o <= 2; o <<= 1) {
#pragma unroll
        for (int k = 0; k < 4; k++) {
            psS[k] += __shfl_xor_sync(0xffffffffu, psS[k], o);
            psD[k] += __shfl_xor_sync(0xffffffffu, psD[k], o);
        }
    }
    if ((lane & 3) == 0) {
        const int q = lane >> 2;
#pragma unroll
        for (int mt = 0; mt < 2; mt++) {
            sredS[wn][wm * 32 + mt * 16 + q]     = psS[mt * 2 + 0];
            sredS[wn][wm * 32 + mt * 16 + q + 8] = psS[mt * 2 + 1];
            sredD[wn][wm * 32 + mt * 16 + q]     = psD[mt * 2 + 0];
            sredD[wn][wm * 32 + mt * 16 + q + 8] = psD[mt * 2 + 1];
        }
    }
    __syncthreads();
    if (tid < 128) {
        const int row = mBase + tid;
        g_as[row * HH + blockIdx.x] = sredS[0][tid] + sredS[1][tid];
        g_ad[row * HH + blockIdx.x] = sredD[0][tid] + sredD[1][tid];
    }
}

// ---------------- CSR build ----------------
__global__ void detect_zero(const int* __restrict__ buf) {
    const int i = blockIdx.x * 256 + threadIdx.x;
    if (i < NN) { g_deg[i] = 0; g_cur[i] = 0; }
    if (blockIdx.x == 0) {
        __shared__ int sh[256];
        int v = 0;
        for (int k = threadIdx.x; k < 8192; k += 256) v |= buf[2 * k + 1];
        sh[threadIdx.x] = v;
        __syncthreads();
        for (int s = 128; s > 0; s >>= 1) {
            if (threadIdx.x < s) sh[threadIdx.x] |= sh[threadIdx.x + s];
            __syncthreads();
        }
        if (threadIdx.x == 0) g_is64 = (sh[0] == 0) ? 1 : 0;
    }
}

__global__ void convert_kernel(const int* __restrict__ buf) {
    const int e = blockIdx.x * blockDim.x + threadIdx.x;
    if (e >= ETOT) return;
    int s, d;
    if (e >= EE) { s = d = e - EE; }
    else if (g_is64) { s = buf[2 * e]; d = buf[2 * (EE + e)]; }
    else             { s = buf[e];     d = buf[EE + e]; }
    g_src[e] = s; g_dst[e] = d;
    atomicAdd(&g_deg[d], 1);
}

__global__ void scan_blocks() {
    const int tid = threadIdx.x, lane = tid & 31, wid = tid >> 5;
    const int i = blockIdx.x * 256 + tid;
    const int v = g_deg[i];
    int x = v;
#pragma unroll
    for (int o = 1; o < 32; o <<= 1) {
        const int y = __shfl_up_sync(0xffffffffu, x, o);
        if (lane >= o) x += y;
    }
    __shared__ int ws[8], wsx[8];
    if (lane == 31) ws[wid] = x;
    __syncthreads();
    if (tid < 8) {
        int ex = 0;
        for (int k = 0; k < tid; k++) ex += ws[k];
        wsx[tid] = ex;
        if (tid == 7) g_bsum[blockIdx.x] = ex + ws[7];
    }
    __syncthreads();
    g_off[i] = wsx[wid] + (x - v);
}

__global__ void scan_bsum() {
    const int tid = threadIdx.x;
    const int v = g_bsum[tid];
    int x = v;
#pragma unroll
    for (int o = 1; o < 32; o <<= 1) {
        const int y = __shfl_up_sync(0xffffffffu, x, o);
        if ((tid & 31) >= o) x += y;
    }
    __shared__ int w0;
    if (tid == 31) w0 = x;
    __syncthreads();
    if (tid >= 32) x += w0;
    g_bsum[tid] = x - v;
    if (tid == 0) g_off[NN] = ETOT;
}

__global__ void scan_add() {
    const int i = blockIdx.x * 256 + threadIdx.x;
    g_off[i] += g_bsum[blockIdx.x];
}

__global__ void scatter_kernel() {
    const int e = blockIdx.x * blockDim.x + threadIdx.x;
    if (e >= ETOT) return;
    const int d = g_dst[e];
    const int pos = atomicAdd(&g_cur[d], 1);
    g_csrc[g_off[d] + pos] = g_src[e];
}

// ---------------- fused softmax + aggregate: warp per (node, head) ----------------
// (R10 structure, 4-way unrolled gather)
__global__ __launch_bounds__(256)
void csr_aggregate(const float* __restrict__ bias, const float* __restrict__ pw, int mode) {
    const int w = blockIdx.x * 8 + (threadIdx.x >> 5);
    const int lane = threadIdx.x & 31;
    const int n = w >> 2, h = w & 3;
    const int off0 = g_off[n];
    const int deg  = g_off[n + 1] - off0;
    const float ad_nh = g_ad[n * HH + h];

    // pass 1: softmax stats
    float m = -1e30f, s = 0.f;
    for (int j = lane; j < deg; j += 32) {
        const int src = g_csrc[off0 + j];
        const float x = lrelu(g_as[src * HH + h] + ad_nh);
        if (x > m) { s = s * __expf(m - x) + 1.f; m = x; } else s += __expf(x - m);
    }
    const float M = wmax(m);
    s *= __expf(m - M);
    const float S = wsum(s);
    const float invd = 1.f / (S + 1e-16f);

    // pass 2: gather (4-way unrolled, fp16 H)
    float4 acc = make_float4(0.f, 0.f, 0.f, 0.f);
    const __half* hbase = g_Hh + h * CC + lane * 4;
    for (int base = 0; base < deg; base += 32) {
        const int cnt = min(32, deg - base);
        int src = 0; float wgt = 0.f;
        if (lane < cnt) {
            src = g_csrc[off0 + base + lane];
            wgt = __expf(lrelu(g_as[src * HH + h] + ad_nh) - M) * invd;
        }
        int j = 0;
        for (; j + 3 < cnt; j += 4) {
            const int   s0 = __shfl_sync(0xffffffffu, src, j);
            const float w0 = __shfl_sync(0xffffffffu, wgt, j);
            const int   s1 = __shfl_sync(0xffffffffu, src, j + 1);
            const float w1 = __shfl_sync(0xffffffffu, wgt, j + 1);
            const int   s2 = __shfl_sync(0xffffffffu, src, j + 2);
            const float w2 = __shfl_sync(0xffffffffu, wgt, j + 2);
            const int   s3 = __shfl_sync(0xffffffffu, src, j + 3);
            const float w3 = __shfl_sync(0xffffffffu, wgt, j + 3);
            const uint2 p0 = *(const uint2*)(hbase + (size_t)s0 * HC);
            const uint2 p1 = *(const uint2*)(hbase + (size_t)s1 * HC);
            const uint2 p2 = *(const uint2*)(hbase + (size_t)s2 * HC);
            const uint2 p3 = *(const uint2*)(hbase + (size_t)s3 * HC);
            const float2 a0 = __half22float2(*(__half2*)&p0.x);
            const float2 b0 = __half22float2(*(__half2*)&p0.y);
            const float2 a1 = __half22float2(*(__half2*)&p1.x);
            const float2 b1 = __half22float2(*(__half2*)&p1.y);
            const float2 a2 = __half22float2(*(__half2*)&p2.x);
            const float2 b2 = __half22float2(*(__half2*)&p2.y);
            const float2 a3 = __half22float2(*(__half2*)&p3.x);
            const float2 b3 = __half22float2(*(__half2*)&p3.y);
            acc.x += a0.x * w0 + a1.x * w1 + a2.x * w2 + a3.x * w3;
            acc.y += a0.y * w0 + a1.y * w1 + a2.y * w2 + a3.y * w3;
            acc.z += b0.x * w0 + b1.x * w1 + b2.x * w2 + b3.x * w3;
            acc.w += b0.y * w0 + b1.y * w1 + b2.y * w2 + b3.y * w3;
        }
        for (; j < cnt; j++) {
            const int   s0 = __shfl_sync(0xffffffffu, src, j);
            const float w0 = __shfl_sync(0xffffffffu, wgt, j);
            const uint2 p0 = *(const uint2*)(hbase + (size_t)s0 * HC);
            const float2 a0 = __half22float2(*(__half2*)&p0.x);
            const float2 b0 = __half22float2(*(__half2*)&p0.y);
            acc.x += a0.x * w0; acc.y += a0.y * w0;
            acc.z += b0.x * w0; acc.w += b0.y * w0;
        }
    }

    const float4 b4 = *(const float4*)&bias[h * CC + lane * 4];
    float4 v = make_float4(acc.x + b4.x, acc.y + b4.y, acc.z + b4.z, acc.w + b4.w);
    v.x = (v.x > 0.f) ? v.x : expm1f(v.x);
    v.y = (v.y > 0.f) ? v.y : expm1f(v.y);
    v.z = (v.z > 0.f) ? v.z : expm1f(v.z);
    v.w = (v.w > 0.f) ? v.w : expm1f(v.w);
    if (mode == 0) {
        const size_t idx = (size_t)n * HC + h * CC + lane * 4;
        *(uint2*)&g_Af[idx] = make_uint2(pack_h2(v.x, v.y), pack_h2(v.z, v.w));
    } else {
        const float4 p = *(const float4*)&pw[h * CC + lane * 4];
        float dot = v.x * p.x + v.y * p.y + v.z * p.z + v.w * p.w;
        dot = wsum(dot);
        if (lane == 0)
            asm volatile("red.global.add.f32 [%0], %1;" :: "l"(&g_x2[n]), "f"(dot) : "memory");
    }
}

// ---------------- x2 init ----------------
__global__ void x2_init(const float* __restrict__ p2b) {
    const int i = blockIdx.x * blockDim.x + threadIdx.x;
    if (i < BB * NODES) g_x2[i] = p2b[0];
}

// ---------------- layer norm ----------------
__global__ void ln_kernel(const float* __restrict__ g, const float* __restrict__ be,
                          float* __restrict__ out) {
    const int bb = blockIdx.x, tid = threadIdx.x;
    const int lane = tid & 31, wid = tid >> 5;
    float s = 0.f, s2 = 0.f;
    for (int i = tid; i < NODES; i += 256) {
        const float v = g_x2[bb * NODES + i];
        s += v; s2 += v * v;
    }
    s = wsum(s); s2 = wsum(s2);
    __shared__ float shs[8], shs2[8];
    if (lane == 0) { shs[wid] = s; shs2[wid] = s2; }
    __syncthreads();
    __shared__ float smu, srv;
    if (tid == 0) {
        float S = 0.f, S2 = 0.f;
        for (int w = 0; w < 8; w++) { S += shs[w]; S2 += shs2[w]; }
        const float mu = S / NODES;
        smu = mu;
        srv = rsqrtf(S2 / NODES - mu * mu + 1e-5f);
    }
    __syncthreads();
    const float mu = smu, rv = srv;
    for (int i = tid; i < NODES; i += 256) {
        const float v = (g_x2[bb * NODES + i] - mu) * rv * g[i] + be[i];
        out[bb * NODES + i] = v;
        g_x2[bb * NODES + i] = v;
    }
}

// ---------------- small FC ----------------
__global__ void fc_kernel(const float* __restrict__ in, const float* __restrict__ W,
                          const float* __restrict__ bias, float* __restrict__ out,
                          int Din, int Dout, int act) {
    const int j = blockIdx.x * blockDim.x + threadIdx.x;
    const int b = blockIdx.y;
    if (j >= Dout) return;
    const float* ir = in + (size_t)b * Din;
    float s = bias[j];
    for (int k = 0; k < Din; k++) s += ir[k] * W[(size_t)k * Dout + j];
    if (act) s = (s > 0.f) ? s : expm1f(s);
    out[b * Dout + j] = s;
}

// ---------------- final ----------------
__global__ void final_kernel(const float* __restrict__ lw, const float* __restrict__ lb,
                             float* __restrict__ out) {
    const int b = blockIdx.x, tid = threadIdx.x;
    const float v = g_e4[b * 64 + tid];
    out[BB * NODES + b * 64 + tid] = v;
    float p = v * lw[tid];
#pragma unroll
    for (int o = 16; o > 0; o >>= 1) p += __shfl_xor_sync(0xffffffffu, p, o);
    __shared__ float sh[2];
    if ((tid & 31) == 0) sh[tid >> 5] = p;
    __syncthreads();
    if (tid == 0) out[BB * NODES + BB * 64 + b] = sh[0] + sh[1] + lb[0];
}

// ---------------- launch ----------------
extern "C" void kernel_launch(void* const* d_in, const int* in_sizes, int n_in,
                              void* d_out, int out_size) {
    const float* x     = (const float*)d_in[0];
    const int*   eibuf = (const int*)d_in[1];
    const float* W1   = (const float*)d_in[3];
    const float* as1  = (const float*)d_in[4];
    const float* ad1  = (const float*)d_in[5];
    const float* b1   = (const float*)d_in[6];
    const float* W2   = (const float*)d_in[7];
    const float* as2  = (const float*)d_in[8];
    const float* ad2  = (const float*)d_in[9];
    const float* b2   = (const float*)d_in[10];
    const float* p2w  = (const float*)d_in[13];
    const float* p2b  = (const float*)d_in[14];
    const float* ln_g = (const float*)d_in[15];
    const float* ln_b = (const float*)d_in[16];
    const float* fw1  = (const float*)d_in[17];
    const float* fb1  = (const float*)d_in[18];
    const float* fw2  = (const float*)d_in[19];
    const float* fb2  = (const float*)d_in[20];
    const float* fw3  = (const float*)d_in[21];
    const float* fb3  = (const float*)d_in[22];
    const float* fw4  = (const float*)d_in[23];
    const float* fb4  = (const float*)d_in[24];
    const float* lw   = (const float*)d_in[25];
    const float* lb   = (const float*)d_in[26];
    float* out = (float*)d_out;

    float *px2, *pe1, *pe2, *pe3, *pe4;
    __half *pHh, *pAf, *pBf;
    cudaGetSymbolAddress((void**)&pHh, g_Hh);
    cudaGetSymbolAddress((void**)&pAf, g_Af);
    cudaGetSymbolAddress((void**)&pBf, g_Bf);
    cudaGetSymbolAddress((void**)&px2, g_x2);
    cudaGetSymbolAddress((void**)&pe1, g_e1);
    cudaGetSymbolAddress((void**)&pe2, g_e2);
    cudaGetSymbolAddress((void**)&pe3, g_e3);
    cudaGetSymbolAddress((void**)&pe4, g_e4);

    cudaFuncSetAttribute(gemm_fp16, cudaFuncAttributeMaxDynamicSharedMemorySize, 65536);

    const int eblocks = (ETOT + 255) / 256;
    const dim3 gemm_grid(HC / 128, NN / 128);

    // launch order: gemm_fp16 (layer 1) at index 3 — the slot ncu actually captures
    cvt_kernel<<<(NN * DIN / 4) / 256, 256>>>(x, pAf);                          // 0
    cvt_kernel<<<(DIN * HC / 4) / 256, 256>>>(W1, pBf);                         // 1
    detect_zero<<<NBLK, 256>>>(eibuf);                                          // 2
    gemm_fp16<<<gemm_grid, 256, 65536>>>(pAf, pBf, pHh, NN, HC, DIN, as1, ad1); // 3  <- profiled
    convert_kernel<<<eblocks, 256>>>(eibuf);                                    // 4
    scan_blocks<<<NBLK, 256>>>();                                               // 5
    scan_bsum<<<1, 64>>>();
    scan_add<<<NBLK, 256>>>();
    scatter_kernel<<<eblocks, 256>>>();
    csr_aggregate<<<NN * HH / 8, 256>>>(b1, nullptr, 0);   // fused softmax+gather -> fp16 h1

    // ===== GAT layer 2 =====
    cvt_kernel<<<(HC * HC / 4) / 256, 256>>>(W2, pBf);
    gemm_fp16<<<gemm_grid, 256, 65536>>>(pAf, pBf, pHh, NN, HC, HC, as2, ad2);
    x2_init<<<(BB * NODES) / 256, 256>>>(p2b);
    csr_aggregate<<<NN * HH / 8, 256>>>(b2, p2w, 1);       // fused pool -> g_x2

    // ===== layer norm -> d_out[0:16384) =====
    ln_kernel<<<BB, 256>>>(ln_g, ln_b, out);

    // ===== encoder MLP =====
    fc_kernel<<<dim3(4, BB), 128>>>(px2, fw1, fb1, pe1, 1024, 512, 1);
    fc_kernel<<<dim3(2, BB), 128>>>(pe1, fw2, fb2, pe2, 512, 256, 1);
    fc_kernel<<<dim3(1, BB), 128>>>(pe2, fw3, fb3, pe3, 256, 128, 1);
    fc_kernel<<<dim3(1, BB), 128>>>(pe3, fw4, fb4, pe4, 128, 64, 1);
    final_kernel<<<BB, 64>>>(lw, lb, out);
}